// round 1
// baseline (speedup 1.0000x reference)
#include <cuda_runtime.h>

// Problem constants
#define NROWS   22743
#define NCH     85
#define NB      64
#define NCELLS  7581          // 76*76 + 38*38 + 19*19
#define BLK     256
#define GX      ((NCELLS + BLK - 1) / BLK)   // 30
#define NBLOCKS (GX * NB)                     // 1920

// Scratch for deterministic two-pass reduction (no dynamic allocation allowed)
__device__ float g_part[NBLOCKS * 4];

// bce(sigmoid(z), t) = t*softplus(-z) + (1-t)*softplus(z) = log(1+e^-z) + (1-t)*z
__device__ __forceinline__ float bce_sig(float z, float t) {
    return __logf(1.0f + __expf(-z)) + (1.0f - t) * z;
}

// bce(p, t) with reference clipping (upper clip 1-1e-12 is a no-op in f32)
__device__ __forceinline__ float bce_raw(float p, float t) {
    float pc = fmaxf(p, 1e-12f);
    return -(t * __logf(pc) + (1.0f - t) * __logf(1.0f - pc));
}

__global__ void __launch_bounds__(BLK)
yolo_pass1(const float* __restrict__ x, const float* __restrict__ tgt) {
    int cell = blockIdx.x * BLK + threadIdx.x;
    int b    = blockIdx.y;

    float s_n = 0.f, s_A = 0.f, s_C = 0.f, s_O = 0.f;

    if (cell < NCELLS) {
        // Per-level constants: grid size, anchors in grid units, 1/(B*fl)
        float g, objw;
        float AW[3], AH[3];
        if (cell < 5776) {              // grid 76, stride 8
            g = 76.f; objw = 1.0f / (64.f * 17328.f);
            AW[0] = 1.25f;    AH[0] = 1.625f;
            AW[1] = 2.0f;     AH[1] = 3.75f;
            AW[2] = 4.125f;   AH[2] = 2.875f;
        } else if (cell < 7220) {       // grid 38, stride 16
            g = 38.f; objw = 1.0f / (64.f * 4332.f);
            AW[0] = 1.875f;   AH[0] = 3.8125f;
            AW[1] = 3.875f;   AH[1] = 2.8125f;
            AW[2] = 3.6875f;  AH[2] = 7.4375f;
        } else {                        // grid 19, stride 32
            g = 19.f; objw = 1.0f / (64.f * 1083.f);
            AW[0] = 3.625f;   AH[0] = 2.8125f;
            AW[1] = 4.875f;   AH[1] = 6.1875f;
            AW[2] = 11.65625f; AH[2] = 10.1875f;
        }

        // Row j0 = 3*cell works globally (level boundaries are multiples of 3)
        size_t base = ((size_t)b * NROWS + (size_t)3 * cell) * NCH;
        const float* xr = x   + base;
        const float* tr = tgt + base;

        float iou[3], x4[3], t4[3], t2a[3], t3a[3];
        #pragma unroll
        for (int k = 0; k < 3; k++) {
            const float* trk = tr + k * NCH;
            float t2 = trk[2], t3 = trk[3];
            t2a[k] = t2; t3a[k] = t3;
            t4[k] = trk[4];
            x4[k] = xr[k * NCH + 4];
            float gw = t2 * g, gh = t3 * g;
            float inter = fminf(gw, AW[k]) * fminf(gh, AH[k]);
            float uni   = gw * gh + AW[k] * AH[k] - inter;
            iou[k] = __fdividef(inter, uni + 1e-12f);
        }

        // jnp.argmax semantics: first index wins ties -> strict >
        int best = 0;
        if (iou[1] > iou[0])    best = 1;
        if (iou[2] > iou[best]) best = 2;

        #pragma unroll
        for (int k = 0; k < 3; k++) {
            float keep = ((iou[k] <= 0.7f) || (k == best)) ? 1.f : 0.f;
            float z  = x4[k] * keep;
            float tt = t4[k] * keep;              // exactly 0 or 1
            // bce(sigmoid(z), tt)
            float bce = __logf(1.0f + __expf(-z)) + (1.0f - tt) * z;
            s_O += bce * objw;

            if (t4[k] > 0.f) {                    // ~2% of rows: masked losses
                s_n += 1.f;
                const float* trk = tr + k * NCH;
                const float* xrk = xr + k * NCH;
                float t0 = trk[0], t1 = trk[1];
                float x0 = xrk[0], x1 = xrk[1], x2 = xrk[2], x3 = xrk[3];
                s_A += bce_sig(x0, t0) + bce_sig(x1, t1);          // xy
                s_A += bce_raw(x2, t2a[k]) + bce_raw(x3, t3a[k]);  // wh
                s_C += bce_sig(x4[k], 1.0f);                       // "cls" (ch 4, t=1)
            }
        }
    }

    // Deterministic fixed-order block reduction
    __shared__ float sm[BLK * 4];
    sm[threadIdx.x]           = s_n;
    sm[threadIdx.x + BLK]     = s_A;
    sm[threadIdx.x + 2 * BLK] = s_C;
    sm[threadIdx.x + 3 * BLK] = s_O;
    __syncthreads();
    #pragma unroll
    for (int off = BLK / 2; off > 0; off >>= 1) {
        if (threadIdx.x < off) {
            sm[threadIdx.x]           += sm[threadIdx.x + off];
            sm[threadIdx.x + BLK]     += sm[threadIdx.x + BLK + off];
            sm[threadIdx.x + 2 * BLK] += sm[threadIdx.x + 2 * BLK + off];
            sm[threadIdx.x + 3 * BLK] += sm[threadIdx.x + 3 * BLK + off];
        }
        __syncthreads();
    }
    if (threadIdx.x == 0) {
        int bid = blockIdx.y * gridDim.x + blockIdx.x;
        g_part[bid * 4 + 0] = sm[0];
        g_part[bid * 4 + 1] = sm[BLK];
        g_part[bid * 4 + 2] = sm[2 * BLK];
        g_part[bid * 4 + 3] = sm[3 * BLK];
    }
}

__global__ void __launch_bounds__(BLK)
yolo_pass2(float* __restrict__ out) {
    __shared__ double sm[BLK * 4];
    double a0 = 0, a1 = 0, a2 = 0, a3 = 0;
    for (int i = threadIdx.x; i < NBLOCKS; i += BLK) {
        a0 += (double)g_part[i * 4 + 0];
        a1 += (double)g_part[i * 4 + 1];
        a2 += (double)g_part[i * 4 + 2];
        a3 += (double)g_part[i * 4 + 3];
    }
    sm[threadIdx.x]           = a0;
    sm[threadIdx.x + BLK]     = a1;
    sm[threadIdx.x + 2 * BLK] = a2;
    sm[threadIdx.x + 3 * BLK] = a3;
    __syncthreads();
    #pragma unroll
    for (int off = BLK / 2; off > 0; off >>= 1) {
        if (threadIdx.x < off) {
            sm[threadIdx.x]           += sm[threadIdx.x + off];
            sm[threadIdx.x + BLK]     += sm[threadIdx.x + BLK + off];
            sm[threadIdx.x + 2 * BLK] += sm[threadIdx.x + 2 * BLK + off];
            sm[threadIdx.x + 3 * BLK] += sm[threadIdx.x + 3 * BLK + off];
        }
        __syncthreads();
    }
    if (threadIdx.x == 0) {
        double n = sm[0];
        if (n < 1.0) n = 1.0;
        double r = sm[BLK] / (2.0 * n)      // loss_xy + loss_wh
                 + sm[2 * BLK] / n          // loss_cls
                 + sm[3 * BLK];             // loss_obj (pre-weighted per level)
        out[0] = (float)r;
    }
}

extern "C" void kernel_launch(void* const* d_in, const int* in_sizes, int n_in,
                              void* d_out, int out_size) {
    const float* x   = (const float*)d_in[0];
    const float* tgt = (const float*)d_in[1];
    dim3 grid(GX, NB);
    yolo_pass1<<<grid, BLK>>>(x, tgt);
    yolo_pass2<<<1, BLK>>>((float*)d_out);
}